// round 1
// baseline (speedup 1.0000x reference)
#include <cuda_runtime.h>
#include <cuda_bf16.h>

// Off-diagonal Gram sum via the identity:
//   sum_{b!=c} (1/D) sum_d x2[b,d] x2[c,d]
//     = (1/D) sum_d [ (sum_b x2[b,d])^2 - sum_b x2[b,d]^2 ]
// where x2 = x*x. Single streaming pass over the input.

#define B_ROWS 32

__device__ double g_acc;

__global__ void zero_acc_kernel() {
    g_acc = 0.0;
}

__global__ void ortho_reduce_kernel(const float4* __restrict__ in, int d4) {
    // one float4 (4 consecutive d) per thread; grid sized to cover d4 exactly
    int idx = blockIdx.x * blockDim.x + threadIdx.x;

    double contrib = 0.0;
    if (idx < d4) {
        float s0 = 0.f, s1 = 0.f, s2 = 0.f, s3 = 0.f;
        float t0 = 0.f, t1 = 0.f, t2 = 0.f, t3 = 0.f;
        #pragma unroll
        for (int b = 0; b < B_ROWS; b++) {
            float4 v = in[(size_t)b * d4 + idx];
            float a0 = v.x * v.x;
            float a1 = v.y * v.y;
            float a2 = v.z * v.z;
            float a3 = v.w * v.w;
            s0 += a0; t0 = fmaf(a0, a0, t0);
            s1 += a1; t1 = fmaf(a1, a1, t1);
            s2 += a2; t2 = fmaf(a2, a2, t2);
            s3 += a3; t3 = fmaf(a3, a3, t3);
        }
        float c = (s0 * s0 - t0) + (s1 * s1 - t1) + (s2 * s2 - t2) + (s3 * s3 - t3);
        contrib = (double)c;
    }

    // block reduction in shared memory (doubles)
    __shared__ double sdata[256];
    int tid = threadIdx.x;
    sdata[tid] = contrib;
    __syncthreads();
    #pragma unroll
    for (int s = 128; s > 0; s >>= 1) {
        if (tid < s) sdata[tid] += sdata[tid + s];
        __syncthreads();
    }
    if (tid == 0) {
        atomicAdd(&g_acc, sdata[0]);
    }
}

__global__ void finalize_kernel(float* out, double inv_d) {
    out[0] = (float)(g_acc * inv_d);
}

extern "C" void kernel_launch(void* const* d_in, const int* in_sizes, int n_in,
                              void* d_out, int out_size) {
    const float4* in = (const float4*)d_in[0];
    float* out = (float*)d_out;

    int total = in_sizes[0];           // 32 * 150528
    int D = total / B_ROWS;            // 150528
    int d4 = D / 4;                    // 37632 = 147 * 256

    zero_acc_kernel<<<1, 1>>>();

    int threads = 256;
    int blocks = (d4 + threads - 1) / threads;   // 147
    ortho_reduce_kernel<<<blocks, threads>>>(in, d4);

    finalize_kernel<<<1, 1>>>(out, 1.0 / (double)D);
}

// round 2
// speedup vs baseline: 1.2000x; 1.2000x over previous
#include <cuda_runtime.h>
#include <cuda_bf16.h>

// Off-diagonal Gram sum via the identity:
//   sum_{b!=c} (1/D) sum_d x2[b,d] x2[c,d]
//     = (1/D) sum_d [ (sum_b x2[b,d])^2 - sum_b x2[b,d]^2 ]
// where x2 = x*x. Single streaming pass, single fused kernel:
// last-block-finalizes pattern (device globals self-reset each run so
// the kernel is replay-deterministic under CUDA graph timing).

#define B_ROWS 32
#define THREADS 256

__device__ double g_acc = 0.0;
__device__ unsigned int g_count = 0;

__global__ void ortho_fused_kernel(const float4* __restrict__ in,
                                   float* __restrict__ out,
                                   int d4, double inv_d) {
    int idx = blockIdx.x * blockDim.x + threadIdx.x;

    double contrib = 0.0;
    if (idx < d4) {
        float s0 = 0.f, s1 = 0.f, s2 = 0.f, s3 = 0.f;
        float t0 = 0.f, t1 = 0.f, t2 = 0.f, t3 = 0.f;
        #pragma unroll
        for (int b = 0; b < B_ROWS; b++) {
            float4 v = in[(size_t)b * d4 + idx];
            float a0 = v.x * v.x;
            float a1 = v.y * v.y;
            float a2 = v.z * v.z;
            float a3 = v.w * v.w;
            s0 += a0; t0 = fmaf(a0, a0, t0);
            s1 += a1; t1 = fmaf(a1, a1, t1);
            s2 += a2; t2 = fmaf(a2, a2, t2);
            s3 += a3; t3 = fmaf(a3, a3, t3);
        }
        float c = (s0 * s0 - t0) + (s1 * s1 - t1) + (s2 * s2 - t2) + (s3 * s3 - t3);
        contrib = (double)c;
    }

    // warp reduction (doubles)
    #pragma unroll
    for (int off = 16; off > 0; off >>= 1)
        contrib += __shfl_down_sync(0xFFFFFFFFu, contrib, off);

    __shared__ double warp_sums[THREADS / 32];
    int lane = threadIdx.x & 31;
    int wid  = threadIdx.x >> 5;
    if (lane == 0) warp_sums[wid] = contrib;
    __syncthreads();

    if (threadIdx.x == 0) {
        double blk = 0.0;
        #pragma unroll
        for (int w = 0; w < THREADS / 32; w++) blk += warp_sums[w];
        atomicAdd(&g_acc, blk);
        __threadfence();
        unsigned int ticket = atomicAdd(&g_count, 1u);
        if (ticket == gridDim.x - 1) {
            // last block to finish: finalize and reset state for next replay
            out[0] = (float)(g_acc * inv_d);
            g_acc = 0.0;
            g_count = 0u;
        }
    }
}

extern "C" void kernel_launch(void* const* d_in, const int* in_sizes, int n_in,
                              void* d_out, int out_size) {
    const float4* in = (const float4*)d_in[0];
    float* out = (float*)d_out;

    int total = in_sizes[0];           // 32 * 150528
    int D = total / B_ROWS;            // 150528
    int d4 = D / 4;                    // 37632 = 147 * 256

    int blocks = (d4 + THREADS - 1) / THREADS;   // 147
    ortho_fused_kernel<<<blocks, THREADS>>>(in, out, d4, 1.0 / (double)D);
}

// round 3
// speedup vs baseline: 1.2043x; 1.0036x over previous
#include <cuda_runtime.h>
#include <cuda_bf16.h>

// Off-diagonal Gram sum via the identity:
//   sum_{b!=c} (1/D) sum_d x2[b,d] x2[c,d]
//     = (1/D) sum_d [ (sum_b x2[b,d])^2 - sum_b x2[b,d]^2 ]
// where x2 = x*x. Single fused kernel, last-block finalizes.
//
// R3 change: batch 16 float4 loads into registers before consuming, so the
// memory pipe sees MLP_p1=16 per thread instead of ~2 (regs=32 previously
// strangled memory-level parallelism; DRAM was at 22.5%).

#define B_ROWS 32
#define THREADS 256
#define BATCH 16

__device__ double g_acc = 0.0;
__device__ unsigned int g_count = 0;

__global__ void __launch_bounds__(THREADS, 1)
ortho_fused_kernel(const float4* __restrict__ in,
                   float* __restrict__ out,
                   int d4, double inv_d) {
    int idx = blockIdx.x * blockDim.x + threadIdx.x;

    double contrib = 0.0;
    if (idx < d4) {
        float s0 = 0.f, s1 = 0.f, s2 = 0.f, s3 = 0.f;
        float t0 = 0.f, t1 = 0.f, t2 = 0.f, t3 = 0.f;

        const float4* p = in + idx;

        #pragma unroll
        for (int grp = 0; grp < B_ROWS / BATCH; grp++) {
            // Stage BATCH independent loads first — no consumption in between,
            // so ptxas front-batches them and the LSU has 16 LDG.128 in flight.
            float4 v[BATCH];
            #pragma unroll
            for (int j = 0; j < BATCH; j++) {
                v[j] = p[(size_t)(grp * BATCH + j) * d4];
            }
            #pragma unroll
            for (int j = 0; j < BATCH; j++) {
                float a0 = v[j].x * v[j].x;
                float a1 = v[j].y * v[j].y;
                float a2 = v[j].z * v[j].z;
                float a3 = v[j].w * v[j].w;
                s0 += a0; t0 = fmaf(a0, a0, t0);
                s1 += a1; t1 = fmaf(a1, a1, t1);
                s2 += a2; t2 = fmaf(a2, a2, t2);
                s3 += a3; t3 = fmaf(a3, a3, t3);
            }
        }
        float c = (s0 * s0 - t0) + (s1 * s1 - t1) + (s2 * s2 - t2) + (s3 * s3 - t3);
        contrib = (double)c;
    }

    // warp reduction (doubles)
    #pragma unroll
    for (int off = 16; off > 0; off >>= 1)
        contrib += __shfl_down_sync(0xFFFFFFFFu, contrib, off);

    __shared__ double warp_sums[THREADS / 32];
    int lane = threadIdx.x & 31;
    int wid  = threadIdx.x >> 5;
    if (lane == 0) warp_sums[wid] = contrib;
    __syncthreads();

    if (threadIdx.x == 0) {
        double blk = 0.0;
        #pragma unroll
        for (int w = 0; w < THREADS / 32; w++) blk += warp_sums[w];
        atomicAdd(&g_acc, blk);
        __threadfence();
        unsigned int ticket = atomicAdd(&g_count, 1u);
        if (ticket == gridDim.x - 1) {
            // last block: finalize and reset state for the next graph replay
            out[0] = (float)(g_acc * inv_d);
            g_acc = 0.0;
            g_count = 0u;
        }
    }
}

extern "C" void kernel_launch(void* const* d_in, const int* in_sizes, int n_in,
                              void* d_out, int out_size) {
    const float4* in = (const float4*)d_in[0];
    float* out = (float*)d_out;

    int total = in_sizes[0];           // 32 * 150528
    int D = total / B_ROWS;            // 150528
    int d4 = D / 4;                    // 37632 = 147 * 256

    int blocks = (d4 + THREADS - 1) / THREADS;   // 147
    ortho_fused_kernel<<<blocks, THREADS>>>(in, out, d4, 1.0 / (double)D);
}